// round 1
// baseline (speedup 1.0000x reference)
#include <cuda_runtime.h>
#include <cstdint>

// ---------------- problem constants (fixed-shape problem) ----------------
#define BATCH   512
#define CH      1024
#define FDIM    14
#define FSQ     196            // FDIM*FDIM
#define NWAY    64
#define KT      64             // K tile (channels per tile)
#define NTILE   (CH / KT)      // 16
#define NPIX    (BATCH * FSQ)  // 100352

// dynamic smem layout (bytes):
//   sQ : KT*FSQ u64 (float2 packed, img0 low / img1 high)   = 100352
//   sP : NWAY*KT u64 (proto value duplicated into both lanes) = 32768
//   sPn: NWAY floats                                          = 256
//   sWs: 8 floats (warp partials)                             = 32
#define SQ_BYTES  (KT * FSQ * 8)
#define SP_BYTES  (NWAY * KT * 8)
#define SMEM_BYTES (SQ_BYTES + SP_BYTES + NWAY * 4 + 64)

// ---------------- device scratch (no allocation allowed) ----------------
__device__ float  g_protos[NWAY * CH];  // gathered prototypes[indices]
__device__ float  g_pn[NWAY];           // ||p_j||^2
__device__ double g_acc;                // loss accumulator

// ---------------- prep: gather protos, norms, zero accumulator ----------
__global__ void dfmn_prep_kernel(const float* __restrict__ protos,
                                 const int*   __restrict__ indices) {
    int j = blockIdx.x;            // class 0..63
    int t = threadIdx.x;           // 256 threads
    int src = indices[j];
    const float* row = protos + (size_t)src * CH;
    float ss = 0.f;
    for (int c = t; c < CH; c += 256) {
        float v = row[c];
        g_protos[j * CH + c] = v;
        ss += v * v;
    }
    #pragma unroll
    for (int o = 16; o > 0; o >>= 1)
        ss += __shfl_down_sync(0xffffffffu, ss, o);
    __shared__ float ws[8];
    if ((t & 31) == 0) ws[t >> 5] = ss;
    __syncthreads();
    if (t == 0) {
        float s = 0.f;
        #pragma unroll
        for (int w = 0; w < 8; w++) s += ws[w];
        g_pn[j] = s;
        if (j == 0) g_acc = 0.0;
    }
}

// ---------------- main: 1 CTA = 2 images, f32x2 packed FMA ----------------
__global__ __launch_bounds__(256, 1)
void dfmn_main_kernel(const float* __restrict__ q,
                      const int*   __restrict__ labels) {
    extern __shared__ char smem_raw[];
    unsigned long long* sQ = reinterpret_cast<unsigned long long*>(smem_raw);
    unsigned long long* sP = reinterpret_cast<unsigned long long*>(smem_raw + SQ_BYTES);
    float* sPn = reinterpret_cast<float*>(smem_raw + SQ_BYTES + SP_BYTES);
    float* sWs = sPn + NWAY;

    const int t  = threadIdx.x;
    const int b0 = blockIdx.x * 2;
    const int b1 = b0 + 1;

    if (t < NWAY) sPn[t] = g_pn[t];
    const int L0 = labels[b0];
    const int L1 = labels[b1];

    // packed accumulators: low lane = image b0, high lane = image b1
    unsigned long long acc[NWAY];
    #pragma unroll
    for (int j = 0; j < NWAY; j++) acc[j] = 0ull;

    const float* qa_base = q + (size_t)b0 * CH * FSQ;
    const float* qb_base = q + (size_t)b1 * CH * FSQ;

    for (int kt = 0; kt < CH; kt += KT) {
        __syncthreads();   // protect smem from previous tile's readers

        // fill prototype tile, value duplicated into both f32 lanes
        for (int i = t; i < NWAY * KT; i += 256) {
            int j = i >> 6;          // KT == 64
            int k = i & (KT - 1);
            float v = g_protos[j * CH + kt + k];
            float2 f2 = make_float2(v, v);
            reinterpret_cast<float2*>(sP)[i] = f2;
        }
        // fill query tile: [k][p] packed {img0, img1}; both streams coalesced
        const float* qa = qa_base + (size_t)kt * FSQ;
        const float* qb = qb_base + (size_t)kt * FSQ;
        for (int i = t; i < KT * FSQ; i += 256) {
            float2 f2 = make_float2(qa[i], qb[i]);
            reinterpret_cast<float2*>(sQ)[i] = f2;
        }
        __syncthreads();

        if (t < FSQ) {
            #pragma unroll 1
            for (int k = 0; k < KT; k++) {
                unsigned long long qv = sQ[k * FSQ + t];
                #pragma unroll
                for (int j = 0; j < NWAY; j++) {
                    unsigned long long pv = sP[j * KT + k];
                    asm volatile("fma.rn.f32x2 %0, %1, %2, %0;"
                                 : "+l"(acc[j]) : "l"(qv), "l"(pv));
                }
            }
        }
    }

    // ---------------- fused log-softmax epilogue (two pixels) -------------
    float loss = 0.f;
    if (t < FSQ) {
        float m0 = -1e30f, m1 = -1e30f;
        #pragma unroll
        for (int j = 0; j < NWAY; j++) {
            float lo = __uint_as_float((unsigned)(acc[j] & 0xffffffffull));
            float hi = __uint_as_float((unsigned)(acc[j] >> 32));
            float pn = sPn[j];
            float s0 = 2.f * lo - pn;
            float s1 = 2.f * hi - pn;
            m0 = fmaxf(m0, s0);
            m1 = fmaxf(m1, s1);
        }
        float e0 = 0.f, e1 = 0.f, sl0 = 0.f, sl1 = 0.f;
        #pragma unroll
        for (int j = 0; j < NWAY; j++) {
            float lo = __uint_as_float((unsigned)(acc[j] & 0xffffffffull));
            float hi = __uint_as_float((unsigned)(acc[j] >> 32));
            float pn = sPn[j];
            float s0 = 2.f * lo - pn;
            float s1 = 2.f * hi - pn;
            e0 += expf(s0 - m0);
            e1 += expf(s1 - m1);
            if (j == L0) sl0 = s0;
            if (j == L1) sl1 = s1;
        }
        // per-pixel NLL = lse - s_label   (the -qn term cancels exactly)
        loss = (m0 + logf(e0) - sl0) + (m1 + logf(e1) - sl1);
    }

    // block reduction -> global double accumulator
    #pragma unroll
    for (int o = 16; o > 0; o >>= 1)
        loss += __shfl_down_sync(0xffffffffu, loss, o);
    if ((t & 31) == 0) sWs[t >> 5] = loss;
    __syncthreads();
    if (t == 0) {
        float s = 0.f;
        #pragma unroll
        for (int w = 0; w < 8; w++) s += sWs[w];
        atomicAdd(&g_acc, (double)s);
    }
}

// ---------------- finalize ----------------
__global__ void dfmn_finalize_kernel(float* out) {
    out[0] = (float)(g_acc * (1.0 / (double)NPIX));
}

// ---------------- launch ----------------
extern "C" void kernel_launch(void* const* d_in, const int* in_sizes, int n_in,
                              void* d_out, int out_size) {
    const float* query   = (const float*)d_in[0];   // [512,1024,14,14] f32
    const int*   labels  = (const int*)  d_in[1];   // [512] i32
    const float* protos  = (const float*)d_in[2];   // [100,1024] f32
    const int*   indices = (const int*)  d_in[3];   // [64] i32
    float* out = (float*)d_out;

    cudaFuncSetAttribute(dfmn_main_kernel,
                         cudaFuncAttributeMaxDynamicSharedMemorySize,
                         SMEM_BYTES);

    dfmn_prep_kernel<<<NWAY, 256>>>(protos, indices);
    dfmn_main_kernel<<<BATCH / 2, 256, SMEM_BYTES>>>(query, labels);
    dfmn_finalize_kernel<<<1, 1>>>(out);
}

// round 2
// speedup vs baseline: 1.8178x; 1.8178x over previous
#include <cuda_runtime.h>
#include <cstdint>

// ---------------- problem constants ----------------
#define BATCH   512
#define CH      1024
#define FSQ     196
#define NWAY    64
#define KT      32              // channels per tile
#define NKT     (CH / KT)       // 32 tiles
#define NPIX    (BATCH * FSQ)

#define NU_IMG  98              // u64 pixel-pairs per image (196/2)
#define NU      196             // u64 pixel-pairs per CTA (2 images)
#define NUP     208             // padded u64 pixels per row
#define QROW    (NUP * 8)       // 1664 B per channel row
#define PROW    (NWAY * 8)      // 512 B per channel row
#define THREADS 416             // 52 pixel-groups x 8 class-groups

#define QBUF_BYTES (KT * QROW)                 // 53248
#define PBUF_BYTES (KT * PROW)                 // 16384
#define SMEM_BYTES (2 * QBUF_BYTES + 2 * PBUF_BYTES)   // 139264

// ---------------- device scratch ----------------
__device__ float              g_pn[NWAY];
__device__ unsigned long long g_protos2[CH * NWAY]; // [c][swizzled j], dup f32x2
__device__ double             g_acc;

// ---------------- prep: gather protos (dup + swizzle), norms, zero acc ----
__global__ void dfmn_prep_kernel(const float* __restrict__ protos,
                                 const int*   __restrict__ indices) {
    int j = blockIdx.x;                 // episode class 0..63
    int t = threadIdx.x;                // 256
    int src = indices[j];
    // u64 swizzle within each 512B row: phys_u64 = j ^ ((j>>4)<<1)
    int jsw = j ^ ((j >> 4) << 1);
    const float* row = protos + (size_t)src * CH;
    float ss = 0.f;
    for (int c = t; c < CH; c += 256) {
        float v = row[c];
        unsigned u = __float_as_uint(v);
        g_protos2[(size_t)c * NWAY + jsw] =
            ((unsigned long long)u << 32) | (unsigned long long)u;
        ss += v * v;
    }
    #pragma unroll
    for (int o = 16; o > 0; o >>= 1)
        ss += __shfl_down_sync(0xffffffffu, ss, o);
    __shared__ float ws[8];
    if ((t & 31) == 0) ws[t >> 5] = ss;
    __syncthreads();
    if (t == 0) {
        float s = 0.f;
        #pragma unroll
        for (int w = 0; w < 8; w++) s += ws[w];
        g_pn[j] = s;
        if (j == 0) g_acc = 0.0;
    }
}

// ---------------- cp.async helpers ----------------
__device__ __forceinline__ void cpa16(uint32_t dst, const void* src) {
    asm volatile("cp.async.cg.shared.global [%0], [%1], 16;\n"
                 :: "r"(dst), "l"(src));
}
__device__ __forceinline__ void cpa_commit() {
    asm volatile("cp.async.commit_group;\n" ::: "memory");
}
template <int N>
__device__ __forceinline__ void cpa_wait() {
    asm volatile("cp.async.wait_group %0;\n" :: "n"(N) : "memory");
}

// ---------------- main kernel ----------------
__global__ __launch_bounds__(THREADS, 1)
void dfmn_main_kernel(const float* __restrict__ q,
                      const int*   __restrict__ labels) {
    extern __shared__ char smem_raw[];
    const uint32_t smem = (uint32_t)__cvta_generic_to_shared(smem_raw);

    const int t  = threadIdx.x;
    const int cg = t & 7;        // class group: classes cg*8 .. cg*8+7
    const int pg = t >> 3;       // pixel group: u64 pixels pg*4 .. pg*4+3
    const int b0 = blockIdx.x * 2;

    // ---- zero padding region of both q buffers (u64 196..207 each row) ----
    for (int i = t; i < 2 * KT * (NUP - NU); i += THREADS) {
        int buf = i / (KT * (NUP - NU));
        int r   = i - buf * (KT * (NUP - NU));
        int k   = r / (NUP - NU);
        int u   = NU + (r - k * (NUP - NU));
        *reinterpret_cast<unsigned long long*>(
            smem_raw + buf * QBUF_BYTES + k * QROW + u * 8) = 0ull;
    }
    __syncthreads();

    // ---- tile loader (cp.async) ----
    auto load_tile = [&](int kt, int buf) {
        const uint32_t qdst0 = smem + buf * QBUF_BYTES;
        const uint32_t pdst0 = smem + 2 * QBUF_BYTES + buf * PBUF_BYTES;
        // query: 32 ch x 2 img x 49 chunks = 3136 x 16B
        for (int i = t; i < KT * 2 * 49; i += THREADS) {
            int k   = i / 98;
            int r   = i - k * 98;
            int img = r / 49;
            int c   = r - img * 49;
            const float* src = q + ((size_t)(b0 + img) * CH + kt * KT + k) * FSQ + c * 4;
            cpa16(qdst0 + k * QROW + img * (NU_IMG * 8) + c * 16, src);
        }
        // protos: 32 ch x 32 chunks = 1024 x 16B (already swizzled in gmem)
        for (int i = t; i < KT * 32; i += THREADS) {
            int k = i >> 5;
            int c = i & 31;
            const void* src = (const char*)g_protos2 + ((size_t)(kt * KT + k) * NWAY) * 8 + c * 16;
            cpa16(pdst0 + k * PROW + c * 16, src);
        }
        cpa_commit();
    };

    // ---- accumulators: acc[c*4 + m] = f32x2 dot for class (cg*8+c), u64-pixel (pg*4+m)
    unsigned long long acc[32];
    #pragma unroll
    for (int i = 0; i < 32; i++) acc[i] = 0ull;

    const uint32_t qbase = smem + pg * 32;
    // pv chunk m physical offset within row: cg*64 + ((m ^ (cg>>1)) * 16)
    const int msw = (cg >> 1) & 3;
    const uint32_t pbase = smem + 2 * QBUF_BYTES + cg * 64;

    load_tile(0, 0);

    for (int kt = 0; kt < NKT; kt++) {
        if (kt + 1 < NKT) load_tile(kt + 1, (kt + 1) & 1);
        if (kt + 1 < NKT) cpa_wait<1>(); else cpa_wait<0>();
        __syncthreads();

        const uint32_t qb = qbase + (kt & 1) * QBUF_BYTES;
        const uint32_t pb = pbase + (kt & 1) * PBUF_BYTES;

        #pragma unroll 4
        for (int k = 0; k < KT; k++) {
            unsigned long long qv[4], pv[8];
            // 2x LDS.128 for 4 u64 pixels
            asm ("ld.shared.v2.u64 {%0,%1}, [%2];"
                 : "=l"(qv[0]), "=l"(qv[1]) : "r"(qb + k * QROW));
            asm ("ld.shared.v2.u64 {%0,%1}, [%2];"
                 : "=l"(qv[2]), "=l"(qv[3]) : "r"(qb + k * QROW + 16));
            // 4x LDS.128 for 8 class values (xor-swizzled chunk order)
            #pragma unroll
            for (int m = 0; m < 4; m++) {
                int mp = m ^ msw;
                asm ("ld.shared.v2.u64 {%0,%1}, [%2];"
                     : "=l"(pv[2 * m]), "=l"(pv[2 * m + 1])
                     : "r"(pb + k * PROW + mp * 16));
            }
            #pragma unroll
            for (int c = 0; c < 8; c++)
                #pragma unroll
                for (int m = 0; m < 4; m++)
                    asm ("fma.rn.f32x2 %0, %1, %2, %0;"
                         : "+l"(acc[c * 4 + m]) : "l"(qv[m]), "l"(pv[c]));
        }
        __syncthreads();
    }

    // ---- per-class norms for this thread's 8 classes ----
    float pn[8];
    #pragma unroll
    for (int c = 0; c < 8; c++) pn[c] = g_pn[cg * 8 + c];

    const int L0 = labels[b0];
    const int L1 = labels[b0 + 1];

    // ---- fused log-softmax epilogue: reduce over cg lanes via shfl_xor ----
    float loss = 0.f;
    #pragma unroll
    for (int m = 0; m < 4; m++) {
        int u     = pg * 4 + m;
        bool valid = (u < NU);
        int  img   = (u >= NU_IMG) ? 1 : 0;
        int  L     = img ? L1 : L0;

        float s0[8], s1[8];
        float m0 = -1e30f, m1 = -1e30f;
        #pragma unroll
        for (int c = 0; c < 8; c++) {
            unsigned long long a = acc[c * 4 + m];
            float lo = __uint_as_float((unsigned)(a & 0xffffffffull));
            float hi = __uint_as_float((unsigned)(a >> 32));
            s0[c] = 2.f * lo - pn[c];
            s1[c] = 2.f * hi - pn[c];
            m0 = fmaxf(m0, s0[c]);
            m1 = fmaxf(m1, s1[c]);
        }
        #pragma unroll
        for (int o = 1; o < 8; o <<= 1) {
            m0 = fmaxf(m0, __shfl_xor_sync(0xffffffffu, m0, o));
            m1 = fmaxf(m1, __shfl_xor_sync(0xffffffffu, m1, o));
        }
        float e0 = 0.f, e1 = 0.f, sl0 = 0.f, sl1 = 0.f;
        #pragma unroll
        for (int c = 0; c < 8; c++) {
            e0 += expf(s0[c] - m0);
            e1 += expf(s1[c] - m1);
            if ((L >> 3) == cg && (L & 7) == c) { sl0 = s0[c]; sl1 = s1[c]; }
        }
        #pragma unroll
        for (int o = 1; o < 8; o <<= 1) {
            e0  += __shfl_xor_sync(0xffffffffu, e0, o);
            e1  += __shfl_xor_sync(0xffffffffu, e1, o);
            sl0 += __shfl_xor_sync(0xffffffffu, sl0, o);
            sl1 += __shfl_xor_sync(0xffffffffu, sl1, o);
        }
        if (valid && cg == 0)
            loss += (m0 + logf(e0) - sl0) + (m1 + logf(e1) - sl1);
    }

    // ---- block reduce -> global double accumulator ----
    #pragma unroll
    for (int o = 16; o > 0; o >>= 1)
        loss += __shfl_down_sync(0xffffffffu, loss, o);
    __shared__ float ws[13];
    if ((t & 31) == 0) ws[t >> 5] = loss;
    __syncthreads();
    if (t == 0) {
        float s = 0.f;
        #pragma unroll
        for (int w = 0; w < 13; w++) s += ws[w];
        atomicAdd(&g_acc, (double)s);
    }
}

// ---------------- finalize ----------------
__global__ void dfmn_finalize_kernel(float* out) {
    out[0] = (float)(g_acc * (1.0 / (double)NPIX));
}

// ---------------- launch ----------------
extern "C" void kernel_launch(void* const* d_in, const int* in_sizes, int n_in,
                              void* d_out, int out_size) {
    const float* query   = (const float*)d_in[0];   // [512,1024,14,14] f32
    const int*   labels  = (const int*)  d_in[1];   // [512] i32
    const float* protos  = (const float*)d_in[2];   // [100,1024] f32
    const int*   indices = (const int*)  d_in[3];   // [64] i32
    float* out = (float*)d_out;

    cudaFuncSetAttribute(dfmn_main_kernel,
                         cudaFuncAttributeMaxDynamicSharedMemorySize,
                         SMEM_BYTES);

    dfmn_prep_kernel<<<NWAY, 256>>>(protos, indices);
    dfmn_main_kernel<<<BATCH / 2, THREADS, SMEM_BYTES>>>(query, labels);
    dfmn_finalize_kernel<<<1, 1>>>(out);
}

// round 4
// speedup vs baseline: 7.0071x; 3.8547x over previous
#include <cuda_runtime.h>
#include <cuda_bf16.h>
#include <cstdint>

// ---------------- problem constants ----------------
#define BATCH   512
#define CH      1024
#define FSQ     196
#define NWAY    64
#define NPIX    (BATCH * FSQ)      // 100352
#define MTILE   128
#define NCTA    (NPIX / MTILE)     // 784 exact
#define THREADS 256
#define BTILE_BYTES 32768          // one k-tile (128 ch) of prepacked B frags
#define SMEM_BYTES  (2 * BTILE_BYTES)

// ---------------- device scratch ----------------
__device__ __align__(16) uint32_t g_pbp[65536];  // [kt][ks][nt][lane]{b0h,b1h,b0l,b1l}
__device__ float  g_pn[NWAY];
__device__ double g_acc;

// ---------------- helpers ----------------
__device__ __forceinline__ void cpa16(uint32_t dst, const void* src) {
    asm volatile("cp.async.cg.shared.global [%0], [%1], 16;" :: "r"(dst), "l"(src));
}
#define CPA_COMMIT() asm volatile("cp.async.commit_group;" ::: "memory")

__device__ __forceinline__ uint32_t pack_bf16x2(float lo, float hi) {
    uint32_t r;
    asm("cvt.rn.bf16x2.f32 %0, %1, %2;" : "=r"(r) : "f"(hi), "f"(lo));
    return r;
}

__device__ __forceinline__ void mma16816(float* d, const uint32_t* a,
                                         uint32_t b0, uint32_t b1) {
    asm volatile(
        "mma.sync.aligned.m16n8k16.row.col.f32.bf16.bf16.f32 "
        "{%0,%1,%2,%3}, {%4,%5,%6,%7}, {%8,%9}, {%0,%1,%2,%3};"
        : "+f"(d[0]), "+f"(d[1]), "+f"(d[2]), "+f"(d[3])
        : "r"(a[0]), "r"(a[1]), "r"(a[2]), "r"(a[3]), "r"(b0), "r"(b1));
}

// ---------------- prep: pack protos into per-thread fragment order ----------
__global__ void dfmn_prep_kernel(const float* __restrict__ protos,
                                 const int*   __restrict__ indices) {
    const int n  = blockIdx.x;           // episode class 0..63
    const int kp = threadIdx.x;          // k-pair 0..511
    const int src = indices[n];
    const int k  = 2 * kp;

    float v0 = protos[(size_t)src * CH + k];
    float v1 = protos[(size_t)src * CH + k + 1];

    uint32_t h = pack_bf16x2(v0, v1);
    float f0 = __uint_as_float(h << 16);
    float f1 = __uint_as_float(h & 0xffff0000u);
    uint32_t l = pack_bf16x2(v0 - f0, v1 - f1);

    const int kt = k >> 7, ks = (k >> 4) & 7, kk = k & 15;
    const int breg = kk >> 3, i = (kk >> 1) & 3;
    const int g = n & 7, nt = n >> 3;
    const int lane = g * 4 + i;
    const int base = ((((kt * 8 + ks) * 8 + nt) * 512) >> 2) + lane * 4;
    g_pbp[base + breg]     = h;
    g_pbp[base + 2 + breg] = l;

    // norms
    float ss = v0 * v0 + v1 * v1;
    #pragma unroll
    for (int o = 16; o > 0; o >>= 1)
        ss += __shfl_down_sync(0xffffffffu, ss, o);
    __shared__ float ws[16];
    if ((kp & 31) == 0) ws[kp >> 5] = ss;
    __syncthreads();
    if (kp == 0) {
        float s = 0.f;
        #pragma unroll
        for (int w = 0; w < 16; w++) s += ws[w];
        g_pn[n] = s;
        if (n == 0) g_acc = 0.0;
    }
}

// ---------------- main kernel ----------------
__global__ __launch_bounds__(THREADS, 2)
void dfmn_main_kernel(const float* __restrict__ q,
                      const int*   __restrict__ labels) {
    extern __shared__ __align__(16) char sm[];
    const uint32_t smb = (uint32_t)__cvta_generic_to_shared(sm);
    __shared__ float s_pn[NWAY];
    __shared__ float s_ws[8];

    const int tid  = threadIdx.x;
    const int w    = tid >> 5;
    const int lane = tid & 31;
    const int g    = lane >> 2;
    const int i    = lane & 3;

    if (tid < NWAY) s_pn[tid] = g_pn[tid];

    // this thread's two pixel rows (m16 fragment rows g, g+8)
    const int Pb = blockIdx.x * MTILE + w * 16;
    const int P0 = Pb + g, P1 = P0 + 8;
    const int b0 = P0 / FSQ, i0 = P0 - b0 * FSQ;
    const int b1 = P1 / FSQ, i1 = P1 - b1 * FSQ;
    // per-thread A pointers, pre-offset by k-slot (2i)*196
    const float* gp0 = q + (size_t)b0 * CH * FSQ + i0 + i * 392;
    const float* gp1 = q + (size_t)b1 * CH * FSQ + i1 + i * 392;

    float acc[8][4];
    #pragma unroll
    for (int nt = 0; nt < 8; nt++)
        #pragma unroll
        for (int r = 0; r < 4; r++) acc[nt][r] = 0.f;

    float st[2][2][8];   // A staging, prefetch distance 2

    auto loadA = [&](int s, float* d) {
        const float* p0 = gp0 + (size_t)s * 3136;   // s*16 channels * 196
        const float* p1 = gp1 + (size_t)s * 3136;
        d[0] = __ldg(p0);        d[1] = __ldg(p0 + 196);
        d[2] = __ldg(p0 + 1568); d[3] = __ldg(p0 + 1764);
        d[4] = __ldg(p1);        d[5] = __ldg(p1 + 196);
        d[6] = __ldg(p1 + 1568); d[7] = __ldg(p1 + 1764);
    };
    auto loadB = [&](int kt, int buf) {
        const char* src = (const char*)g_pbp + (size_t)kt * BTILE_BYTES;
        uint32_t dst = smb + buf * BTILE_BYTES;
        #pragma unroll
        for (int c = 0; c < 8; c++) {
            int idx = tid + c * THREADS;
            cpa16(dst + idx * 16, src + idx * 16);
        }
        CPA_COMMIT();
    };

    loadB(0, 0);
    loadA(0, st[0][0]);
    loadA(1, st[1][0]);
    __syncthreads();

    for (int kt = 0; kt < 8; kt++) {
        if (kt < 7) {
            loadB(kt + 1, (kt + 1) & 1);
            asm volatile("cp.async.wait_group 1;" ::: "memory");
        } else {
            asm volatile("cp.async.wait_group 0;" ::: "memory");
        }
        __syncthreads();

        const uint32_t bb = smb + (kt & 1) * BTILE_BYTES + lane * 16;

        #pragma unroll
        for (int ks = 0; ks < 8; ks++) {
            const int s = kt * 8 + ks;
            if (s + 2 < 64)
                loadA(s + 2, st[ks & 1][((ks >> 1) + 1) & 1]);
            const float* av = st[ks & 1][(ks >> 1) & 1];

            // A fragments: hi + residual lo
            uint32_t ah[4], al[4];
            {
                const int prx[4] = {0, 4, 2, 6};   // a0:P0klo a1:P1klo a2:P0khi a3:P1khi
                #pragma unroll
                for (int r = 0; r < 4; r++) {
                    float x = av[prx[r]], y = av[prx[r] + 1];
                    ah[r] = pack_bf16x2(x, y);
                    float xh = __uint_as_float(ah[r] << 16);
                    float yh = __uint_as_float(ah[r] & 0xffff0000u);
                    al[r] = pack_bf16x2(x - xh, y - yh);
                }
            }

            #pragma unroll
            for (int nt = 0; nt < 8; nt++) {
                uint32_t bh0, bh1, bl0, bl1;
                asm("ld.shared.v4.u32 {%0,%1,%2,%3}, [%4];"
                    : "=r"(bh0), "=r"(bh1), "=r"(bl0), "=r"(bl1)
                    : "r"(bb + ks * 4096 + nt * 512));
                mma16816(acc[nt], ah, bh0, bh1);   // qh . ph
                mma16816(acc[nt], al, bh0, bh1);   // ql . ph
                mma16816(acc[nt], ah, bl0, bl1);   // qh . pl
            }
        }
        __syncthreads();
    }

    // ---------------- fused log-softmax epilogue ----------------
    const int L0v = labels[b0];
    const int L1v = labels[b1];

    float m0 = -1e30f, m1 = -1e30f;
    #pragma unroll
    for (int nt = 0; nt < 8; nt++) {
        float pna = s_pn[nt * 8 + 2 * i];
        float pnb = s_pn[nt * 8 + 2 * i + 1];
        acc[nt][0] = 2.f * acc[nt][0] - pna;
        acc[nt][1] = 2.f * acc[nt][1] - pnb;
        acc[nt][2] = 2.f * acc[nt][2] - pna;
        acc[nt][3] = 2.f * acc[nt][3] - pnb;
        m0 = fmaxf(m0, fmaxf(acc[nt][0], acc[nt][1]));
        m1 = fmaxf(m1, fmaxf(acc[nt][2], acc[nt][3]));
    }
    #pragma unroll
    for (int o = 1; o < 4; o <<= 1) {
        m0 = fmaxf(m0, __shfl_xor_sync(0xffffffffu, m0, o));
        m1 = fmaxf(m1, __shfl_xor_sync(0xffffffffu, m1, o));
    }
    float e0 = 0.f, e1 = 0.f, sl0 = 0.f, sl1 = 0.f;
    #pragma unroll
    for (int nt = 0; nt < 8; nt++) {
        e0 += __expf(acc[nt][0] - m0) + __expf(acc[nt][1] - m0);
        e1 += __expf(acc[nt][2] - m1) + __expf(acc[nt][3] - m1);
        int c0 = nt * 8 + 2 * i, c1 = c0 + 1;
        if (c0 == L0v) sl0 = acc[nt][0];
        if (c1 == L0v) sl0 = acc[nt][1];
        if (c0 == L1v) sl1 = acc[nt][2];
        if (c1 == L1v) sl1 = acc[nt][3];
    }
    #pragma unroll
    for (int o = 1; o < 4; o <<= 1) {
        e0  += __shfl_xor_sync(0xffffffffu, e0, o);
        e1  += __shfl_xor_sync(0xffffffffu, e1, o);
        sl0 += __shfl_xor_sync(0xffffffffu, sl0, o);
        sl1 += __shfl_xor_sync(0xffffffffu, sl1, o);
    }
    float loss = (i == 0)
        ? (m0 + __logf(e0) - sl0) + (m1 + __logf(e1) - sl1) : 0.f;

    #pragma unroll
    for (int o = 16; o > 0; o >>= 1)
        loss += __shfl_down_sync(0xffffffffu, loss, o);
    if (lane == 0) s_ws[w] = loss;
    __syncthreads();
    if (tid == 0) {
        float s = 0.f;
        #pragma unroll
        for (int ww = 0; ww < 8; ww++) s += s_ws[ww];
        atomicAdd(&g_acc, (double)s);
    }
}

// ---------------- finalize ----------------
__global__ void dfmn_finalize_kernel(float* out) {
    out[0] = (float)(g_acc * (1.0 / (double)NPIX));
}

// ---------------- launch ----------------
extern "C" void kernel_launch(void* const* d_in, const int* in_sizes, int n_in,
                              void* d_out, int out_size) {
    const float* query   = (const float*)d_in[0];   // [512,1024,14,14] f32
    const int*   labels  = (const int*)  d_in[1];   // [512] i32
    const float* protos  = (const float*)d_in[2];   // [100,1024] f32
    const int*   indices = (const int*)  d_in[3];   // [64] i32
    float* out = (float*)d_out;

    cudaFuncSetAttribute(dfmn_main_kernel,
                         cudaFuncAttributeMaxDynamicSharedMemorySize,
                         SMEM_BYTES);

    dfmn_prep_kernel<<<NWAY, 512>>>(protos, indices);
    dfmn_main_kernel<<<NCTA, THREADS, SMEM_BYTES>>>(query, labels);
    dfmn_finalize_kernel<<<1, 1>>>(out);
}